// round 17
// baseline (speedup 1.0000x reference)
#include <cuda_runtime.h>
#include <cuda_bf16.h>

// x = (N=2, C=16, D=96, H=128, W=128) fp32; out = concat(gx, gy, gz).
// Per-warp private cp.async pipelines: each warp streams its own 3 rows
// through a 4-stage smem ring (6KB/warp), self-synced via wait_group --
// NO __syncthreads in the main loop. Register z-rings + shuffle x-halo +
// __stcs stores as in the best kernel. One wave of 512 CTAs.

#define W_   128
#define H_   128
#define D_   96
#define NC_  32
#define YT_  8
#define HW_  (H_ * W_)
#define CST_ (D_ * HW_)
#define V_   (NC_ * CST_)
#define STG_ 4

__global__ __launch_bounds__(256, 4)
void sobel3d_kernel(const float* __restrict__ in, float* __restrict__ out) {
    __shared__ float sm[YT_][STG_][3][W_];    // 48 KB, warp-private slices

    const int lane = threadIdx.x;                    // 0..31
    const int wy   = threadIdx.y;                    // 0..7 (warp id / row)
    const int y    = blockIdx.x * YT_ + wy;          // 0..127
    const int nc   = blockIdx.y;                     // 0..31
    const int x4   = lane * 4;

    const float* src = in + nc * CST_;
    float* gx = out;
    float* gy = out + V_;
    float* gz = out + 2 * V_;

    const bool ym_ok = (y > 0);
    const bool yp_ok = (y < H_ - 1);
    const int rm_off = (y - 1) * W_ + x4;
    const int r0_off = y * W_ + x4;
    const int rp_off = (y + 1) * W_ + x4;
    const int obase  = nc * CST_ + y * W_ + x4;

    // Pre-zero this warp's OOB row slots across all stages (never overwritten).
    if (!ym_ok) {
        #pragma unroll
        for (int st = 0; st < STG_; ++st)
            *reinterpret_cast<float4*>(&sm[wy][st][0][x4]) = make_float4(0,0,0,0);
    }
    if (!yp_ok) {
        #pragma unroll
        for (int st = 0; st < STG_; ++st)
            *reinterpret_cast<float4*>(&sm[wy][st][2][x4]) = make_float4(0,0,0,0);
    }

    // Per-warp producer: plane p -> stage p&3 (3 rows, 16B per lane per row).
    auto load_plane = [&](int p) {
        const int st = p & (STG_ - 1);
        const float* pl = src + p * HW_;
        if (ym_ok) {
            unsigned int d = (unsigned int)__cvta_generic_to_shared(&sm[wy][st][0][x4]);
            asm volatile("cp.async.cg.shared.global [%0], [%1], 16;\n" :: "r"(d), "l"(pl + rm_off));
        }
        {
            unsigned int d = (unsigned int)__cvta_generic_to_shared(&sm[wy][st][1][x4]);
            asm volatile("cp.async.cg.shared.global [%0], [%1], 16;\n" :: "r"(d), "l"(pl + r0_off));
        }
        if (yp_ok) {
            unsigned int d = (unsigned int)__cvta_generic_to_shared(&sm[wy][st][2][x4]);
            asm volatile("cp.async.cg.shared.global [%0], [%1], 16;\n" :: "r"(d), "l"(pl + rp_off));
        }
        asm volatile("cp.async.commit_group;\n");
    };

    load_plane(0);
    load_plane(1);
    load_plane(2);

    // z rings of per-plane y-convolutions: s = smooth_y, d = deriv_y
    float4 zz = make_float4(0.f, 0.f, 0.f, 0.f);
    float4 s_m = zz, s_0 = zz, d_m = zz, d_0 = zz;

    #pragma unroll 3
    for (int pz = 0; pz <= D_; ++pz) {
        float4 rm, r0, rp;
        if (pz < D_) {
            asm volatile("cp.async.wait_group 2;\n" ::: "memory");
            const int st = pz & (STG_ - 1);
            rm = *reinterpret_cast<const float4*>(&sm[wy][st][0][x4]);
            r0 = *reinterpret_cast<const float4*>(&sm[wy][st][1][x4]);
            rp = *reinterpret_cast<const float4*>(&sm[wy][st][2][x4]);
            if (pz + 3 < D_) load_plane(pz + 3);
            else asm volatile("cp.async.commit_group;\n");
        } else {
            rm = zz; r0 = zz; rp = zz;
        }

        float4 s_p, d_p;
        d_p.x = rp.x - rm.x; d_p.y = rp.y - rm.y;
        d_p.z = rp.z - rm.z; d_p.w = rp.w - rm.w;
        s_p.x = rm.x + 2.f * r0.x + rp.x;
        s_p.y = rm.y + 2.f * r0.y + rp.y;
        s_p.z = rm.z + 2.f * r0.z + rp.z;
        s_p.w = rm.w + 2.f * r0.w + rp.w;

        if (pz >= 1) {
            float4 Sz, Dz, Zc;
            Sz.x = s_m.x + 2.f * s_0.x + s_p.x;
            Sz.y = s_m.y + 2.f * s_0.y + s_p.y;
            Sz.z = s_m.z + 2.f * s_0.z + s_p.z;
            Sz.w = s_m.w + 2.f * s_0.w + s_p.w;
            Dz.x = d_m.x + 2.f * d_0.x + d_p.x;
            Dz.y = d_m.y + 2.f * d_0.y + d_p.y;
            Dz.z = d_m.z + 2.f * d_0.z + d_p.z;
            Dz.w = d_m.w + 2.f * d_0.w + d_p.w;
            Zc.x = s_p.x - s_m.x; Zc.y = s_p.y - s_m.y;
            Zc.z = s_p.z - s_m.z; Zc.w = s_p.w - s_m.w;

            float SzL = __shfl_up_sync(0xffffffffu, Sz.w, 1);
            float SzR = __shfl_down_sync(0xffffffffu, Sz.x, 1);
            float DzL = __shfl_up_sync(0xffffffffu, Dz.w, 1);
            float DzR = __shfl_down_sync(0xffffffffu, Dz.x, 1);
            float ZcL = __shfl_up_sync(0xffffffffu, Zc.w, 1);
            float ZcR = __shfl_down_sync(0xffffffffu, Zc.x, 1);
            if (lane == 0)  { SzL = 0.f; DzL = 0.f; ZcL = 0.f; }
            if (lane == 31) { SzR = 0.f; DzR = 0.f; ZcR = 0.f; }

            float4 vx, vy, vz;
            vx.x = Sz.y - SzL;  vx.y = Sz.z - Sz.x;
            vx.z = Sz.w - Sz.y; vx.w = SzR  - Sz.z;
            vy.x = DzL  + 2.f * Dz.x + Dz.y;
            vy.y = Dz.x + 2.f * Dz.y + Dz.z;
            vy.z = Dz.y + 2.f * Dz.z + Dz.w;
            vy.w = Dz.z + 2.f * Dz.w + DzR;
            vz.x = ZcL  + 2.f * Zc.x + Zc.y;
            vz.y = Zc.x + 2.f * Zc.y + Zc.z;
            vz.z = Zc.y + 2.f * Zc.z + Zc.w;
            vz.w = Zc.z + 2.f * Zc.w + ZcR;

            const int o = obase + (pz - 1) * HW_;
            __stcs(reinterpret_cast<float4*>(gx + o), vx);
            __stcs(reinterpret_cast<float4*>(gy + o), vy);
            __stcs(reinterpret_cast<float4*>(gz + o), vz);
        }
        s_m = s_0; s_0 = s_p;
        d_m = d_0; d_0 = d_p;
    }
}

extern "C" void kernel_launch(void* const* d_in, const int* in_sizes, int n_in,
                              void* d_out, int out_size) {
    const float* x = (const float*)d_in[0];
    float* out = (float*)d_out;

    dim3 block(32, YT_, 1);            // 256 threads
    dim3 grid(H_ / YT_, NC_, 1);       // 512 blocks, one wave
    sobel3d_kernel<<<grid, block>>>(x, out);
}